// round 6
// baseline (speedup 1.0000x reference)
#include <cuda_runtime.h>

#define BATCH 4
#define DD 160
#define HH 192
#define WW 160
#define HW (HH * WW)                 // 30720
#define VOX (DD * HH * WW)           // 4,915,200
#define TOTAL (BATCH * VOX)          // 19,660,800
#define NPAIR (TOTAL / 2)            // 9,830,400
#define PPROW (WW / 2)               // 80 pairs per row
#define TPB 256

// One w-pair per thread. Shared aligned float2-window gather with inline
// w-overflow handling (k1==3) and a rows-mismatch-only scalar fallback.
__global__ __launch_bounds__(TPB, 6) void st_affine_trilinear_v6(
    const float* __restrict__ vol,   // [B, D, H, W]
    const float* __restrict__ trf,   // [B, 4, 4]
    float* __restrict__ out)         // [B, D, H, W]
{
    const int g = blockIdx.x * TPB + threadIdx.x;

    const int row = g / PPROW;
    const int w0  = (g - row * PPROW) * 2;

    const int b  = row / (DD * HH);
    const int r  = row - b * (DD * HH);
    const int d  = r / HH;
    const int h  = r - d * HH;

    const float* A = trf + b * 16;
    const float a00 = A[0], a01 = A[1], a02 = A[2],  a03 = A[3];
    const float a10 = A[4], a11 = A[5], a12 = A[6],  a13 = A[7];
    const float a20 = A[8], a21 = A[9], a22 = A[10], a23 = A[11];

    const float cD = (DD - 1) * 0.5f, cH = (HH - 1) * 0.5f, cW = (WW - 1) * 0.5f;
    const float pd  = (float)d - cD;
    const float ph  = (float)h - cH;
    const float pw0 = (float)w0 - cW;

    const float mD = (float)(DD - 1), mH = (float)(HH - 1), mW = (float)(WW - 1);
    const float* v = vol + b * VOX;

    // ---- voxel 0 ----
    const float ld0 = fmaf(a00, pd, fmaf(a01, ph, fmaf(a02, pw0, a03))) + cD;
    const float lh0 = fmaf(a10, pd, fmaf(a11, ph, fmaf(a12, pw0, a13))) + cH;
    const float lw0 = fmaf(a20, pd, fmaf(a21, ph, fmaf(a22, pw0, a23))) + cW;

    const float td0 = fminf(fmaxf(ld0, 0.0f), mD);
    const float th0 = fminf(fmaxf(lh0, 0.0f), mH);
    const float tw0 = fminf(fmaxf(lw0, 0.0f), mW);
    const float f0d0 = fminf(floorf(td0), mD - 1.0f);
    const float f0h0 = fminf(floorf(th0), mH - 1.0f);
    const float f0w0 = fminf(floorf(tw0), mW - 1.0f);
    const float w0d0 = (f0d0 - td0) + 1.0f;
    const float w0h0 = (f0h0 - th0) + 1.0f;
    const float w0w0 = (f0w0 - tw0) + 1.0f;
    const int c0   = (int)(fmaf(f0d0, (float)HW, fmaf(f0h0, (float)WW, f0w0)));
    const int i0w0 = (int)f0w0;

    // ---- voxel 1 ----
    const float ld1 = ld0 + a02;
    const float lh1 = lh0 + a12;
    const float lw1 = lw0 + a22;

    const float td1 = fminf(fmaxf(ld1, 0.0f), mD);
    const float th1 = fminf(fmaxf(lh1, 0.0f), mH);
    const float tw1 = fminf(fmaxf(lw1, 0.0f), mW);
    const float f0d1 = fminf(floorf(td1), mD - 1.0f);
    const float f0h1 = fminf(floorf(th1), mH - 1.0f);
    const float f0w1 = fminf(floorf(tw1), mW - 1.0f);
    const float w0d1 = (f0d1 - td1) + 1.0f;
    const float w0h1 = (f0h1 - th1) + 1.0f;
    const float w0w1 = (f0w1 - tw1) + 1.0f;
    const int c1 = (int)(fmaf(f0d1, (float)HW, fmaf(f0h1, (float)WW, f0w1)));

    // ---- shared aligned float2 window [e .. e+3] on voxel0's rows ----
    const int e  = c0 & ~1;
    const int k0 = c0 - e;                     // {0,1}
    const int dc = c1 - c0;                    // rows same  <=>  dc in [0,3]
    const int k1 = c1 - e;                     // {0..3} when rows same (k0 + dw)
    const int qbs = (i0w0 < 158) ? 1 : 0;      // avoid reading past row end

    const float2* p = reinterpret_cast<const float2*>(v + e);
    const float2 qa00 = __ldg(p);
    const float2 qb00 = __ldg(p + qbs);
    const float2 qa01 = __ldg(p + (WW / 2));
    const float2 qb01 = __ldg(p + (WW / 2) + qbs);
    const float2 qa10 = __ldg(p + (HW / 2));
    const float2 qb10 = __ldg(p + (HW / 2) + qbs);
    const float2 qa11 = __ldg(p + ((HW + WW) / 2));
    const float2 qb11 = __ldg(p + ((HW + WW) / 2) + qbs);

    // ---- voxel 0 corner values ----
    const bool o0 = (k0 != 0);
    const float x00a = o0 ? qa00.y : qa00.x, x00b = o0 ? qb00.x : qa00.y;
    const float x01a = o0 ? qa01.y : qa01.x, x01b = o0 ? qb01.x : qa01.y;
    const float x10a = o0 ? qa10.y : qa10.x, x10b = o0 ? qb10.x : qa10.y;
    const float x11a = o0 ? qa11.y : qa11.x, x11b = o0 ? qb11.x : qa11.y;

    float e00 = fmaf(w0w0, x00a - x00b, x00b);
    float e01 = fmaf(w0w0, x01a - x01b, x01b);
    float e10 = fmaf(w0w0, x10a - x10b, x10b);
    float e11 = fmaf(w0w0, x11a - x11b, x11b);
    float eh0 = fmaf(w0h0, e00 - e01, e01);
    float eh1 = fmaf(w0h0, e10 - e11, e11);
    const float r0 = fmaf(w0d0, eh0 - eh1, eh1);

    // ---- voxel 1 corner values ----
    // Inline w-overflow (k1==3): only the '+1' element per row is outside
    // the window; fetch it with a per-lane predicated scalar load (~1 wf).
    const bool rows_same = ((unsigned)dc <= 3u);
    const bool s1 = (k1 >= 1), s2 = (k1 >= 2);
    const bool s3 = rows_same && (k1 == 3);

    float fx00 = 0.f, fx01 = 0.f, fx10 = 0.f, fx11 = 0.f;
    if (s3) {
        fx00 = __ldg(v + c1 + 1);
        fx01 = __ldg(v + c1 + WW + 1);
        fx10 = __ldg(v + c1 + HW + 1);
        fx11 = __ldg(v + c1 + HW + WW + 1);
    }

    float y00a = s3 ? qb00.y : (s2 ? qb00.x : (s1 ? qa00.y : qa00.x));
    float y00b = s3 ? fx00   : (s2 ? qb00.y : (s1 ? qb00.x : qa00.y));
    float y01a = s3 ? qb01.y : (s2 ? qb01.x : (s1 ? qa01.y : qa01.x));
    float y01b = s3 ? fx01   : (s2 ? qb01.y : (s1 ? qb01.x : qa01.y));
    float y10a = s3 ? qb10.y : (s2 ? qb10.x : (s1 ? qa10.y : qa10.x));
    float y10b = s3 ? fx10   : (s2 ? qb10.y : (s1 ? qb10.x : qa10.y));
    float y11a = s3 ? qb11.y : (s2 ? qb11.x : (s1 ? qa11.y : qa11.x));
    float y11b = s3 ? fx11   : (s2 ? qb11.y : (s1 ? qb11.x : qa11.y));

    if (!rows_same) {
        // voxel1's corner rows differ from voxel0's (~8% of lanes)
        y00a = __ldg(v + c1);
        y00b = __ldg(v + c1 + 1);
        y01a = __ldg(v + c1 + WW);
        y01b = __ldg(v + c1 + WW + 1);
        y10a = __ldg(v + c1 + HW);
        y10b = __ldg(v + c1 + HW + 1);
        y11a = __ldg(v + c1 + HW + WW);
        y11b = __ldg(v + c1 + HW + WW + 1);
    }

    float g00 = fmaf(w0w1, y00a - y00b, y00b);
    float g01 = fmaf(w0w1, y01a - y01b, y01b);
    float g10 = fmaf(w0w1, y10a - y10b, y10b);
    float g11 = fmaf(w0w1, y11a - y11b, y11b);
    float gh0 = fmaf(w0h1, g00 - g01, g01);
    float gh1 = fmaf(w0h1, g10 - g11, g11);
    const float r1 = fmaf(w0d1, gh0 - gh1, gh1);

    float2 res;
    res.x = r0;
    res.y = r1;
    *reinterpret_cast<float2*>(out + row * WW + w0) = res;
}

extern "C" void kernel_launch(void* const* d_in, const int* in_sizes, int n_in,
                              void* d_out, int out_size) {
    const float* vol = (const float*)d_in[0];
    const float* trf = (const float*)d_in[1];
    float* out = (float*)d_out;
    const int blocks = NPAIR / TPB;   // 38400, exact
    st_affine_trilinear_v6<<<blocks, TPB>>>(vol, trf, out);
}